// round 2
// baseline (speedup 1.0000x reference)
#include <cuda_runtime.h>

// TemporalAttentionModel: B=16, T=48, N=500, D=64, K=8 heads, d=8
// Fully fused per-(b,n) kernel, fp32 with packed f32x2 FMA (FFMA2).

#define B_  16
#define T_  48
#define N_  500
#define D_  64
#define HD_ 128   // 2*D
#define Q3_ 192   // 3*D
#define NTHR 384

typedef unsigned long long u64;

__device__ __forceinline__ u64 pack2(float x, float y) {
    u64 r;
    asm("mov.b64 %0, {%1, %2};" : "=l"(r) : "f"(x), "f"(y));
    return r;
}
__device__ __forceinline__ void unpack2(u64 v, float& x, float& y) {
    asm("mov.b64 {%0, %1}, %2;" : "=f"(x), "=f"(y) : "l"(v));
}
__device__ __forceinline__ u64 fma2(u64 a, u64 b, u64 c) {
    u64 d;
    asm("fma.rn.f32x2 %0, %1, %2, %3;" : "=l"(d) : "l"(a), "l"(b), "l"(c));
    return d;
}

// Shared memory layout (floats):
//  Hs    : 48*128        = 6144
//  Ws    : 128*192       = 24576   (QKV weights; later reused: W15 at [0,4096), W16 at [4096,8192))
//  qkvs  : 3*48*64       = 9216    (q,k,v; q region reused as Z later)
//  aos   : 48*64         = 3072
//  biasq : 192, b15s: 64, b16s: 64 = 320
static const int SMEM_FLOATS = 6144 + 24576 + 9216 + 3072 + 320;
static const int SMEM_BYTES  = SMEM_FLOATS * 4;   // 173,312 B -> 1 CTA/SM

__global__ __launch_bounds__(NTHR, 1)
void fused_temporal_attn(const float* __restrict__ X, const float* __restrict__ STE,
                         const float* __restrict__ W12, const float* __restrict__ b12,
                         const float* __restrict__ W13, const float* __restrict__ b13,
                         const float* __restrict__ W14, const float* __restrict__ b14,
                         const float* __restrict__ W15, const float* __restrict__ b15,
                         const float* __restrict__ W16, const float* __restrict__ b16,
                         float* __restrict__ out)
{
    extern __shared__ float sm[];
    float* Hs    = sm;                    // [48][128]
    float* Ws    = Hs + 6144;             // [128][192] then reused for W15|W16
    float* qkvs  = Ws + 24576;            // q:[0,3072) k:[3072,6144) v:[6144,9216)
    float* aos   = qkvs + 9216;           // [48][64]
    float* biasq = aos + 3072;            // [192]
    float* b15s  = biasq + 192;           // [64]
    float* b16s  = b15s + 64;             // [64]

    const int n   = blockIdx.x;
    const int b   = blockIdx.y;
    const int tid = threadIdx.x;

    // ------------------------------------------------------------------
    // Stage 1: load H = [X | STE] rows for this (b, n), and W12|W13|W14
    // ------------------------------------------------------------------
    {
        // H: 48 rows; X part = 16 float4, STE part = 16 float4 per row
        const float4* X4   = (const float4*)X;
        const float4* STE4 = (const float4*)STE;
        float4* H4 = (float4*)Hs;
        for (int id = tid; id < 768; id += NTHR) {
            int t = id >> 4;
            int c = id & 15;
            int base = ((b * T_ + t) * N_ + n) * 16 + c;  // float4 units
            H4[t * 32 + c]      = X4[base];
            H4[t * 32 + 16 + c] = STE4[base];
        }
        // Weights: Ws[i*192 + m*64 + j] = Wm[i*64 + j]; 6144 float4 total
        const float4* Wsrc[3] = { (const float4*)W12, (const float4*)W13, (const float4*)W14 };
        float4* W4 = (float4*)Ws;
        for (int id = tid; id < 6144; id += NTHR) {
            int i  = id / 48;
            int r  = id - i * 48;
            int m  = r >> 4;
            int j4 = r & 15;
            W4[i * 48 + r] = Wsrc[m][i * 16 + j4];
        }
        if (tid < 64) {
            biasq[tid]       = b12[tid];
            biasq[64 + tid]  = b13[tid];
            biasq[128 + tid] = b14[tid];
            b15s[tid]        = b15[tid];
            b16s[tid]        = b16[tid];
        }
    }
    __syncthreads();

    // ------------------------------------------------------------------
    // Stage 2: QKV = relu(H @ [W12|W13|W14] + bias)   [48 x 192]
    // Tiling: thread = (rg, cg): rows 4*rg..+3, cols 6*cg..+5
    // FFMA2 over column pairs.
    // ------------------------------------------------------------------
    {
        const int cg = tid & 31;
        const int rg = tid >> 5;
        const int c0 = cg * 6;
        u64 acc[4][3];
        {
            u64 bp0 = *(const u64*)&biasq[c0];
            u64 bp1 = *(const u64*)&biasq[c0 + 2];
            u64 bp2 = *(const u64*)&biasq[c0 + 4];
            #pragma unroll
            for (int r = 0; r < 4; r++) { acc[r][0] = bp0; acc[r][1] = bp1; acc[r][2] = bp2; }
        }
        const float* h0 = &Hs[(rg * 4) * HD_];

        #pragma unroll 4
        for (int i = 0; i < HD_; i += 4) {
            float h[4][4];
            #pragma unroll
            for (int r = 0; r < 4; r++)
                *(float4*)h[r] = *(const float4*)&h0[r * HD_ + i];
            #pragma unroll
            for (int ii = 0; ii < 4; ii++) {
                const float* wrow = &Ws[(i + ii) * Q3_ + c0];
                u64 w0 = *(const u64*)&wrow[0];
                u64 w1 = *(const u64*)&wrow[2];
                u64 w2 = *(const u64*)&wrow[4];
                #pragma unroll
                for (int r = 0; r < 4; r++) {
                    u64 hp = pack2(h[r][ii], h[r][ii]);
                    acc[r][0] = fma2(hp, w0, acc[r][0]);
                    acc[r][1] = fma2(hp, w1, acc[r][1]);
                    acc[r][2] = fma2(hp, w2, acc[r][2]);
                }
            }
        }
        // relu + scatter into q/k/v
        #pragma unroll
        for (int r = 0; r < 4; r++) {
            int row = rg * 4 + r;
            #pragma unroll
            for (int p = 0; p < 3; p++) {
                float x0, x1;
                unpack2(acc[r][p], x0, x1);
                x0 = fmaxf(x0, 0.0f);
                x1 = fmaxf(x1, 0.0f);
                int j  = c0 + 2 * p;        // even; pair never straddles a 64-col boundary
                int m  = j >> 6;
                int jj = j & 63;
                *(float2*)&qkvs[m * 3072 + row * 64 + jj] = make_float2(x0, x1);
            }
        }
    }
    __syncthreads();

    // ------------------------------------------------------------------
    // Stage 3: preload W15|W16 into Ws (overwrites QKV weights; no reader left)
    // Overlaps with attention compute below; consumed after next barrier.
    // ------------------------------------------------------------------
    {
        const float4* W15_4 = (const float4*)W15;
        const float4* W16_4 = (const float4*)W16;
        float4* W4 = (float4*)Ws;
        for (int id = tid; id < 2048; id += NTHR)
            W4[id] = (id < 1024) ? W15_4[id] : W16_4[id - 1024];
    }

    // ------------------------------------------------------------------
    // Stage 4: attention. thread = (t1, head); scores [48] live in regs.
    // ------------------------------------------------------------------
    {
        const int head = tid & 7;
        const int t1   = tid >> 3;
        const float* qrow = &qkvs[t1 * 64 + head * 8];
        u64 qp[4];
        #pragma unroll
        for (int j = 0; j < 4; j++) qp[j] = *(const u64*)&qrow[2 * j];

        const float scale = 0.35355339059327373f;  // 1/sqrt(8)
        float sc[T_];
        const float* kb = &qkvs[3072 + head * 8];
        #pragma unroll
        for (int t2 = 0; t2 < T_; t2++) {
            const u64* kr = (const u64*)&kb[t2 * 64];
            u64 s2 = 0;  // (+0.0f, +0.0f)
            s2 = fma2(qp[0], kr[0], s2);
            s2 = fma2(qp[1], kr[1], s2);
            s2 = fma2(qp[2], kr[2], s2);
            s2 = fma2(qp[3], kr[3], s2);
            float lo, hi;
            unpack2(s2, lo, hi);
            sc[t2] = (lo + hi) * scale;
        }
        float mx = sc[0];
        #pragma unroll
        for (int t2 = 1; t2 < T_; t2++) mx = fmaxf(mx, sc[t2]);
        float sum = 0.0f;
        #pragma unroll
        for (int t2 = 0; t2 < T_; t2++) {
            float e = __expf(sc[t2] - mx);
            sc[t2] = e;
            sum += e;
        }
        float inv = 1.0f / sum;

        u64 o[4] = {0, 0, 0, 0};
        const float* vb = &qkvs[6144 + head * 8];
        #pragma unroll
        for (int t2 = 0; t2 < T_; t2++) {
            u64 p2 = pack2(sc[t2], sc[t2]);
            const u64* vr = (const u64*)&vb[t2 * 64];
            o[0] = fma2(p2, vr[0], o[0]);
            o[1] = fma2(p2, vr[1], o[1]);
            o[2] = fma2(p2, vr[2], o[2]);
            o[3] = fma2(p2, vr[3], o[3]);
        }
        float* ao = &aos[t1 * 64 + head * 8];
        #pragma unroll
        for (int j = 0; j < 4; j++) {
            float x0, x1;
            unpack2(o[j], x0, x1);
            *(float2*)&ao[2 * j] = make_float2(x0 * inv, x1 * inv);
        }
    }
    __syncthreads();   // aos complete; W15/W16 loads complete

    // ------------------------------------------------------------------
    // Stage 5: Z = relu(aos @ W15 + b15) -> reuse q region as Z
    // Tiling: thread = (rg, cg): rows 4*rg..+3, col pair 2*cg
    // ------------------------------------------------------------------
    float* Zs = qkvs;  // [48][64]
    {
        const int cg = tid & 31;
        const int rg = tid >> 5;
        const int c0 = cg * 2;
        u64 acc[4];
        {
            u64 bz = *(const u64*)&b15s[c0];
            #pragma unroll
            for (int r = 0; r < 4; r++) acc[r] = bz;
        }
        const float* h0 = &aos[(rg * 4) * 64];
        #pragma unroll 4
        for (int i = 0; i < 64; i += 4) {
            float h[4][4];
            #pragma unroll
            for (int r = 0; r < 4; r++)
                *(float4*)h[r] = *(const float4*)&h0[r * 64 + i];
            #pragma unroll
            for (int ii = 0; ii < 4; ii++) {
                u64 w = *(const u64*)&Ws[(i + ii) * 64 + c0];
                #pragma unroll
                for (int r = 0; r < 4; r++)
                    acc[r] = fma2(pack2(h[r][ii], h[r][ii]), w, acc[r]);
            }
        }
        #pragma unroll
        for (int r = 0; r < 4; r++) {
            float x0, x1;
            unpack2(acc[r], x0, x1);
            *(float2*)&Zs[(rg * 4 + r) * 64 + c0] =
                make_float2(fmaxf(x0, 0.0f), fmaxf(x1, 0.0f));
        }
    }
    __syncthreads();

    // ------------------------------------------------------------------
    // Stage 6: out = Z @ W16 + b16 -> global (coalesced float2 stores)
    // ------------------------------------------------------------------
    {
        const int cg = tid & 31;
        const int rg = tid >> 5;
        const int c0 = cg * 2;
        const float* w16s = Ws + 4096;
        u64 acc[4];
        {
            u64 bz = *(const u64*)&b16s[c0];
            #pragma unroll
            for (int r = 0; r < 4; r++) acc[r] = bz;
        }
        const float* h0 = &Zs[(rg * 4) * 64];
        #pragma unroll 4
        for (int i = 0; i < 64; i += 4) {
            float h[4][4];
            #pragma unroll
            for (int r = 0; r < 4; r++)
                *(float4*)h[r] = *(const float4*)&h0[r * 64 + i];
            #pragma unroll
            for (int ii = 0; ii < 4; ii++) {
                u64 w = *(const u64*)&w16s[(i + ii) * 64 + c0];
                #pragma unroll
                for (int r = 0; r < 4; r++)
                    acc[r] = fma2(pack2(h[r][ii], h[r][ii]), w, acc[r]);
            }
        }
        #pragma unroll
        for (int r = 0; r < 4; r++) {
            int row = rg * 4 + r;
            float x0, x1;
            unpack2(acc[r], x0, x1);
            *(float2*)&out[((b * T_ + row) * N_ + n) * 64 + c0] = make_float2(x0, x1);
        }
    }
}

extern "C" void kernel_launch(void* const* d_in, const int* in_sizes, int n_in,
                              void* d_out, int out_size) {
    (void)in_sizes; (void)n_in; (void)out_size;
    cudaFuncSetAttribute(fused_temporal_attn,
                         cudaFuncAttributeMaxDynamicSharedMemorySize, SMEM_BYTES);
    const float* X   = (const float*)d_in[0];
    const float* STE = (const float*)d_in[1];
    const float* W12 = (const float*)d_in[2];
    const float* b12 = (const float*)d_in[3];
    const float* W13 = (const float*)d_in[4];
    const float* b13 = (const float*)d_in[5];
    const float* W14 = (const float*)d_in[6];
    const float* b14 = (const float*)d_in[7];
    const float* W15 = (const float*)d_in[8];
    const float* b15 = (const float*)d_in[9];
    const float* W16 = (const float*)d_in[10];
    const float* b16 = (const float*)d_in[11];
    float* out = (float*)d_out;

    dim3 grid(N_, B_);
    fused_temporal_attn<<<grid, NTHR, SMEM_BYTES>>>(
        X, STE, W12, b12, W13, b13, W14, b14, W15, b15, W16, b16, out);
}